// round 16
// baseline (speedup 1.0000x reference)
#include <cuda_runtime.h>
#include <cuda_fp16.h>
#include <math.h>
#include <stdint.h>

#define NN 50000
#define EE 1600000
#define ET (EE + NN)
#define HID 128
#define FIN 39

#define SCAN_B 256
#define SCAN_CH ((NN + SCAN_B - 1) / SCAN_B)  // 196 nodes per scan block

// ---------------- scratch (device globals; no allocation allowed) ----------------
__device__ float g_h[NN * HID];
__device__ __half g_hf16[NN * HID];  // fp16 mirror of h (A-feed for all GEMMs)
__device__ __half g_xph[NN * HID];   // fp16 xp (gather is the only consumer)
__device__ float g_es[NN * 4];
__device__ float g_ed[NN * 4];
__device__ float g_w[ET * 4 + 32];   // per-edge per-head softmax numerators
__device__ int g_deg[NN];
__device__ int g_rowstart[NN + 1];
__device__ int g_cursor[NN];
__device__ int g_csrc[ET];
__device__ int g_cdst[ET];
__device__ int g_bsum[SCAN_B];
// pre-converted fp16 weight images, linear [N][K]
__device__ __half g_w16[6 * 128 * 128];
__device__ __half g_w1h[128 * 48];  // enc_w1 hi, [N=128][K=48] (39 real + pad)
__device__ __half g_w1l[128 * 48];  // enc_w1 lo

// ---------------- CSR build (deg zeroed in prep_w_k; self-loop folded in as +1) ----------------
__global__ void count_k(const int* __restrict__ ei) {
    int idx = blockIdx.x * blockDim.x + threadIdx.x;  // 4 edges each
    int e0 = idx * 4;
    if (e0 >= EE) return;
    int4 d = *(const int4*)(ei + EE + e0);
    atomicAdd(&g_deg[d.x], 1);
    atomicAdd(&g_deg[d.y], 1);
    atomicAdd(&g_deg[d.z], 1);
    atomicAdd(&g_deg[d.w], 1);
}

// phase 1: per-block chunk sums of (deg+1)
__global__ void __launch_bounds__(256) partial_k() {
    __shared__ int ws[8];
    int b = blockIdx.x, t = threadIdx.x;
    int lo = b * SCAN_CH, hi = min(lo + SCAN_CH, NN);
    int s = 0;
    for (int i = lo + t; i < hi; i += 256) s += g_deg[i] + 1;
#pragma unroll
    for (int off = 16; off >= 1; off >>= 1) s += __shfl_xor_sync(0xffffffffu, s, off);
    if ((t & 31) == 0) ws[t >> 5] = s;
    __syncthreads();
    if (t < 8) {
        int v = ws[t];
#pragma unroll
        for (int off = 4; off >= 1; off >>= 1) v += __shfl_xor_sync(0xffu, v, off);
        if (t == 0) g_bsum[b] = v;
    }
}

// phase 2+3 merged: each block reduces bsum[0..b-1] itself, then local re-scan + write
__global__ void __launch_bounds__(256) fill_k() {
    __shared__ int sh[256];
    __shared__ int part[8];
    int b = blockIdx.x, t = threadIdx.x;
    {
        int v = (t < b) ? g_bsum[t] : 0;
#pragma unroll
        for (int off = 16; off >= 1; off >>= 1) v += __shfl_xor_sync(0xffffffffu, v, off);
        if ((t & 31) == 0) part[t >> 5] = v;
    }
    if (b == 0 && t == 0) g_rowstart[NN] = ET;
    int lo = b * SCAN_CH, hi = min(lo + SCAN_CH, NN);
    const int CH2 = (SCAN_CH + 255) / 256;  // 1
    int mylo = lo + t * CH2;
    int myhi = min(mylo + CH2, hi);
    int s = 0;
    for (int i = mylo; i < myhi; i++) s += g_deg[i] + 1;
    sh[t] = s;
    __syncthreads();
    for (int off = 1; off < 256; off <<= 1) {
        int u = (t >= off) ? sh[t - off] : 0;
        __syncthreads();
        sh[t] += u;
        __syncthreads();
    }
    int pbase = 0;
#pragma unroll
    for (int j = 0; j < 8; j++) pbase += part[j];
    int base = pbase + ((t == 0) ? 0 : sh[t - 1]);
    for (int i = mylo; i < myhi; i++) {
        g_rowstart[i] = base;
        g_csrc[base] = i;  // self-loop
        g_cdst[base] = i;
        g_cursor[i] = base + 1;
        base += g_deg[i] + 1;
    }
}

__global__ void scatter_k(const int* __restrict__ ei) {
    int idx = blockIdx.x * blockDim.x + threadIdx.x;  // 4 edges each
    int e0 = idx * 4;
    if (e0 >= EE) return;
    int4 sv = *(const int4*)(ei + e0);
    int4 dv = *(const int4*)(ei + EE + e0);
    int p0 = atomicAdd(&g_cursor[dv.x], 1);
    g_csrc[p0] = sv.x; g_cdst[p0] = dv.x;
    int p1 = atomicAdd(&g_cursor[dv.y], 1);
    g_csrc[p1] = sv.y; g_cdst[p1] = dv.y;
    int p2 = atomicAdd(&g_cursor[dv.z], 1);
    g_csrc[p2] = sv.z; g_cdst[p2] = dv.z;
    int p3 = atomicAdd(&g_cursor[dv.w], 1);
    g_csrc[p3] = sv.w; g_cdst[p3] = dv.w;
}

// ---------------- weight prep (+ deg zero) ----------------
__global__ void __launch_bounds__(256) prep_w_k(const float* __restrict__ w0,
                                                const float* __restrict__ w1,
                                                const float* __restrict__ w2,
                                                const float* __restrict__ w3,
                                                const float* __restrict__ w4,
                                                const float* __restrict__ w5,
                                                const float* __restrict__ we1) {
    int m = blockIdx.x;
    if (m >= 7) {  // blocks 7.. zero g_deg
        int b = m - 7;
        int lo = b * SCAN_CH, hi = min(lo + SCAN_CH, NN);
        for (int i = lo + threadIdx.x; i < hi; i += 256) g_deg[i] = 0;
        return;
    }
    if (m == 6) {
        for (int i = threadIdx.x; i < 128 * 48; i += 256) {
            int n = i / 48, k = i % 48;
            float v = (k < FIN) ? we1[k * 128 + n] : 0.f;
            __half h = __float2half_rn(v);
            g_w1h[i] = h;
            g_w1l[i] = __float2half_rn(v - __half2float(h));
        }
        return;
    }
    const float* Wm[6] = {w0, w1, w2, w3, w4, w5};
    const int ncs[6] = {128, 128, 128, 128, 64, 64};
    const int bases[6] = {0, 16384, 32768, 49152, 65536, 65536 + 8192};  // imp+tim packed
    const float* B = Wm[m];
    int NC = ncs[m];
    __half* dst = g_w16 + bases[m];
    int total = NC * 128;
    for (int i = threadIdx.x; i < total; i += 256) {
        int n = i >> 7, k = i & 127;
        dst[i] = __float2half_rn(B[k * NC + n]);
    }
}

// ---------------- HMMA GEMM core pieces (single-pass fp16) ----------------
#define LDB 272   // padded smem row stride, K=128 tiles
#define LDA1 112  // padded smem row stride, K=48 tiles

#define MMA16816(d, A0, A1, A2, A3, B0, B1)                                     \
    asm volatile(                                                               \
        "mma.sync.aligned.m16n8k16.row.col.f32.f16.f16.f32 "                    \
        "{%0,%1,%2,%3}, {%4,%5,%6,%7}, {%8,%9}, {%0,%1,%2,%3};"                 \
        : "+f"((d)[0]), "+f"((d)[1]), "+f"((d)[2]), "+f"((d)[3])                \
        : "r"(A0), "r"(A1), "r"(A2), "r"(A3), "r"(B0), "r"(B1))

// fill A (pre-converted fp16 mirror) + B (pre-converted) into padded smem — pure copies
template <int NC>
__device__ __forceinline__ void gemm_fill16(const __half* A16, const __half* B16,
                                            char* sA, char* sB,
                                            int rb, int nrows, int tid) {
    for (int i = tid; i < 128 * 16; i += 256) {
        int r = i >> 4, u = i & 15;
        uint4 v = make_uint4(0, 0, 0, 0);
        if (rb + r < nrows) v = *(const uint4*)(A16 + (rb + r) * 128 + u * 8);
        *(uint4*)(sA + r * LDB + u * 16) = v;
    }
    for (int i = tid; i < NC * 16; i += 256) {
        int n = i >> 4, k8 = (i & 15) * 8;
        *(uint4*)(sB + n * LDB + k8 * 2) = ((const uint4*)B16)[i];
    }
}

template <int NCH>
__device__ __forceinline__ void gemm_main(const char* sA, const char* sB,
                                          int lrow0, int g, int t, float acc[][4]) {
#pragma unroll
    for (int n = 0; n < NCH; n++)
#pragma unroll
        for (int j = 0; j < 4; j++) acc[n][j] = 0.f;
#pragma unroll
    for (int ks = 0; ks < 8; ks++) {
        int kb = ks * 32 + t * 4;
        const char* pa = sA + lrow0 * LDB + kb;
        uint32_t a0 = *(const uint32_t*)(pa);
        uint32_t a1 = *(const uint32_t*)(pa + 8 * LDB);
        uint32_t a2 = *(const uint32_t*)(pa + 16);
        uint32_t a3 = *(const uint32_t*)(pa + 8 * LDB + 16);
#pragma unroll
        for (int n = 0; n < NCH; n++) {
            int col = n * 8 + g;
            const char* pb = sB + col * LDB + kb;
            uint32_t b0 = *(const uint32_t*)(pb);
            uint32_t b1 = *(const uint32_t*)(pb + 16);
            MMA16816(acc[n], a0, a1, a2, a3, b0, b1);
        }
    }
}

// ---------------- fused encoder: relu(x@W1+b1)@W2 + b2 in one block pass ----------------
__global__ void __launch_bounds__(256, 2) enc_fused_k(const float* __restrict__ x,
                                                      const float* __restrict__ b1,
                                                      const __half* __restrict__ w2,
                                                      const float* __restrict__ b2,
                                                      float* __restrict__ H, int nrows) {
    extern __shared__ char smem[];
    char* sA1h = smem;             // 128*112 = 14336
    char* sA1l = smem + 14336;
    char* sB1h = smem + 28672;
    char* sB1l = smem + 43008;
    __shared__ float sb1[128];

    int tid = threadIdx.x;
    int rb = blockIdx.x * 128;
    if (tid < 128) sb1[tid] = b1[tid];

    for (int i = tid; i < 14336 / 16; i += 256) {
        ((uint4*)sA1h)[i] = make_uint4(0, 0, 0, 0);
        ((uint4*)sA1l)[i] = make_uint4(0, 0, 0, 0);
    }
    for (int i = tid; i < 128 * 6; i += 256) {
        int n = i / 6, u = i % 6;
        *(uint4*)(sB1h + n * LDA1 + u * 16) = ((const uint4*)g_w1h)[i];
        *(uint4*)(sB1l + n * LDA1 + u * 16) = ((const uint4*)g_w1l)[i];
    }
    __syncthreads();
    for (int i = tid; i < 128 * FIN; i += 256) {
        int r = i / FIN, c = i % FIN;
        float v = (rb + r < nrows) ? x[(rb + r) * FIN + c] : 0.f;
        __half h = __float2half_rn(v);
        *(__half*)(sA1h + r * LDA1 + c * 2) = h;
        *(__half*)(sA1l + r * LDA1 + c * 2) = __float2half_rn(v - __half2float(h));
    }
    __syncthreads();

    int wid = tid >> 5, lane = tid & 31;
    int g = lane >> 2, t = lane & 3;
    int lrow0 = wid * 16 + g;

    float acc[16][4];
#pragma unroll
    for (int n = 0; n < 16; n++)
#pragma unroll
        for (int j = 0; j < 4; j++) acc[n][j] = 0.f;

#pragma unroll
    for (int ks = 0; ks < 3; ks++) {
        int kb = ks * 32 + t * 4;
        const char* ph = sA1h + lrow0 * LDA1 + kb;
        uint32_t ah0 = *(const uint32_t*)(ph);
        uint32_t ah1 = *(const uint32_t*)(ph + 8 * LDA1);
        uint32_t ah2 = *(const uint32_t*)(ph + 16);
        uint32_t ah3 = *(const uint32_t*)(ph + 8 * LDA1 + 16);
        const char* pl = sA1l + lrow0 * LDA1 + kb;
        uint32_t al0 = *(const uint32_t*)(pl);
        uint32_t al1 = *(const uint32_t*)(pl + 8 * LDA1);
        uint32_t al2 = *(const uint32_t*)(pl + 16);
        uint32_t al3 = *(const uint32_t*)(pl + 8 * LDA1 + 16);
#pragma unroll
        for (int n = 0; n < 16; n++) {
            int col = n * 8 + g;
            const char* pbh = sB1h + col * LDA1 + kb;
            uint32_t bh0 = *(const uint32_t*)(pbh);
            uint32_t bh1 = *(const uint32_t*)(pbh + 16);
            const char* pbl = sB1l + col * LDA1 + kb;
            uint32_t bl0 = *(const uint32_t*)(pbl);
            uint32_t bl1 = *(const uint32_t*)(pbl + 16);
            MMA16816(acc[n], ah0, ah1, ah2, ah3, bh0, bh1);
            MMA16816(acc[n], ah0, ah1, ah2, ah3, bl0, bl1);
            MMA16816(acc[n], al0, al1, al2, al3, bh0, bh1);
        }
    }
    __syncthreads();

    char* sA2 = smem;
    char* sB2 = smem + 34816;
#pragma unroll
    for (int n = 0; n < 16; n++) {
        int col = n * 8 + t * 2;
        float v0 = fmaxf(acc[n][0] + sb1[col], 0.f);
        float v1 = fmaxf(acc[n][1] + sb1[col + 1], 0.f);
        float v2 = fmaxf(acc[n][2] + sb1[col], 0.f);
        float v3 = fmaxf(acc[n][3] + sb1[col + 1], 0.f);
        __half2 p0 = __floats2half2_rn(v0, v1);
        __half2 p1 = __floats2half2_rn(v2, v3);
        *(__half2*)(sA2 + lrow0 * LDB + col * 2) = p0;
        *(__half2*)(sA2 + (lrow0 + 8) * LDB + col * 2) = p1;
    }
    for (int i = tid; i < 128 * 16; i += 256) {
        int n = i >> 4, k8 = (i & 15) * 8;
        *(uint4*)(sB2 + n * LDB + k8 * 2) = ((const uint4*)w2)[i];
    }
    __syncthreads();

    float acc2[16][4];
    gemm_main<16>(sA2, sB2, lrow0, g, t, acc2);

    int grow0 = rb + lrow0, grow1 = grow0 + 8;
#pragma unroll
    for (int n = 0; n < 16; n++) {
        int col = n * 8 + t * 2;
        float b0 = __ldg(b2 + col), b1v = __ldg(b2 + col + 1);
        float o0 = acc2[n][0] + b0, o1 = acc2[n][1] + b1v;
        float o2 = acc2[n][2] + b0, o3 = acc2[n][3] + b1v;
        if (grow0 < nrows) {
            *(float2*)(H + grow0 * 128 + col) = make_float2(o0, o1);
            __half2 m0 = __floats2half2_rn(o0, o1);
            *(__half2*)(g_hf16 + grow0 * 128 + col) = m0;
        }
        if (grow1 < nrows) {
            *(float2*)(H + grow1 * 128 + col) = make_float2(o2, o3);
            __half2 m1 = __floats2half2_rn(o2, o3);
            *(__half2*)(g_hf16 + grow1 * 128 + col) = m1;
        }
    }
}

// main GEMM (ATTN): A from fp16 mirror; writes fp16 xp + es/ed (no esmax needed)
template <int NC>
__global__ void __launch_bounds__(256, 2) mma_gemm_k(const __half* __restrict__ A16,
                                                     const __half* __restrict__ B16,
                                                     const float* __restrict__ a_s,
                                                     const float* __restrict__ a_d,
                                                     int nrows) {
    extern __shared__ char smem[];
    char* sA = smem;            // 128*272 = 34816
    char* sB = smem + 34816;    // NC*272

    int tid = threadIdx.x;
    int rb = blockIdx.x * 128;
    gemm_fill16<NC>(A16, B16, sA, sB, rb, nrows, tid);
    __syncthreads();

    int wid = tid >> 5, lane = tid & 31;
    int g = lane >> 2, t = lane & 3;
    int lrow0 = wid * 16 + g;
    constexpr int NCH = NC / 8;
    float acc[NCH][4];
    gemm_main<NCH>(sA, sB, lrow0, g, t, acc);

    int grow0 = rb + lrow0, grow1 = grow0 + 8;

    float es0[4], ed0[4], es1[4], ed1[4];
#pragma unroll
    for (int h = 0; h < 4; h++) { es0[h] = 0.f; ed0[h] = 0.f; es1[h] = 0.f; ed1[h] = 0.f; }
#pragma unroll
    for (int n = 0; n < NCH; n++) {
        int col = n * 8 + t * 2;
        int h = n >> 2;
        float as0 = __ldg(a_s + col), as1 = __ldg(a_s + col + 1);
        float ad0 = __ldg(a_d + col), ad1 = __ldg(a_d + col + 1);
        es0[h] += acc[n][0] * as0 + acc[n][1] * as1;
        ed0[h] += acc[n][0] * ad0 + acc[n][1] * ad1;
        es1[h] += acc[n][2] * as0 + acc[n][3] * as1;
        ed1[h] += acc[n][2] * ad0 + acc[n][3] * ad1;
    }
#pragma unroll
    for (int h = 0; h < 4; h++) {
        es0[h] += __shfl_xor_sync(0xffffffffu, es0[h], 1);
        es0[h] += __shfl_xor_sync(0xffffffffu, es0[h], 2);
        ed0[h] += __shfl_xor_sync(0xffffffffu, ed0[h], 1);
        ed0[h] += __shfl_xor_sync(0xffffffffu, ed0[h], 2);
        es1[h] += __shfl_xor_sync(0xffffffffu, es1[h], 1);
        es1[h] += __shfl_xor_sync(0xffffffffu, es1[h], 2);
        ed1[h] += __shfl_xor_sync(0xffffffffu, ed1[h], 1);
        ed1[h] += __shfl_xor_sync(0xffffffffu, ed1[h], 2);
    }
    if (t == 0) {
        if (grow0 < nrows) {
#pragma unroll
            for (int h = 0; h < 4; h++) {
                g_es[grow0 * 4 + h] = es0[h];
                g_ed[grow0 * 4 + h] = ed0[h];
            }
        }
        if (grow1 < nrows) {
#pragma unroll
            for (int h = 0; h < 4; h++) {
                g_es[grow1 * 4 + h] = es1[h];
                g_ed[grow1 * 4 + h] = ed1[h];
            }
        }
    }
#pragma unroll
    for (int n = 0; n < NCH; n++) {
        int col = n * 8 + t * 2;
        __half2 p0 = __floats2half2_rn(acc[n][0], acc[n][1]);
        __half2 p1 = __floats2half2_rn(acc[n][2], acc[n][3]);
        if (grow0 < nrows) *(__half2*)(g_xph + grow0 * NC + col) = p0;
        if (grow1 < nrows) *(__half2*)(g_xph + grow1 * NC + col) = p1;
    }
}

// ---------------- softplus ----------------
__device__ __forceinline__ float softplusf(float x) {
    if (x > 20.f) return x;
    return log1pf(__expf(x));
}

// fused heads: GEMM([imp_w1|tim_w1]) + relu + second-layer dots + softplus
__global__ void __launch_bounds__(256, 2) mma_heads_k(const __half* __restrict__ A16,
                                                      const __half* __restrict__ B16,
                                                      const float* __restrict__ biasA,
                                                      const float* __restrict__ biasB,
                                                      const float* __restrict__ w2i,
                                                      const float* __restrict__ b2i,
                                                      const float* __restrict__ w2t,
                                                      const float* __restrict__ b2t,
                                                      float* __restrict__ out,
                                                      int nrows) {
    extern __shared__ char smem[];
    char* sA = smem;
    char* sB = smem + 34816;
    __shared__ float swi[192];
    __shared__ float swt[128];
    __shared__ float sbias[128];

    int tid = threadIdx.x;
    if (tid < 192) swi[tid] = w2i[tid];
    if (tid < 128) swt[tid] = w2t[tid];
    if (tid < 64) sbias[tid] = biasA[tid];
    else if (tid < 128) sbias[tid] = biasB[tid - 64];

    int rb = blockIdx.x * 128;
    gemm_fill16<128>(A16, B16, sA, sB, rb, nrows, tid);
    __syncthreads();

    int wid = tid >> 5, lane = tid & 31;
    int g = lane >> 2, t = lane & 3;
    int lrow0 = wid * 16 + g;
    float acc[16][4];
    gemm_main<16>(sA, sB, lrow0, g, t, acc);

    float i0a = 0.f, i1a = 0.f, i2a = 0.f, t0a = 0.f, t1a = 0.f;
    float i0b = 0.f, i1b = 0.f, i2b = 0.f, t0b = 0.f, t1b = 0.f;
#pragma unroll
    for (int n = 0; n < 16; n++) {
        int col = n * 8 + t * 2;
        float bb0 = sbias[col], bb1 = sbias[col + 1];
        float hA0 = fmaxf(acc[n][0] + bb0, 0.f), hA1 = fmaxf(acc[n][1] + bb1, 0.f);
        float hB0 = fmaxf(acc[n][2] + bb0, 0.f), hB1 = fmaxf(acc[n][3] + bb1, 0.f);
        if (col < 64) {
            int c = col;
            i0a = fmaf(hA0, swi[c * 3 + 0], fmaf(hA1, swi[(c + 1) * 3 + 0], i0a));
            i1a = fmaf(hA0, swi[c * 3 + 1], fmaf(hA1, swi[(c + 1) * 3 + 1], i1a));
            i2a = fmaf(hA0, swi[c * 3 + 2], fmaf(hA1, swi[(c + 1) * 3 + 2], i2a));
            i0b = fmaf(hB0, swi[c * 3 + 0], fmaf(hB1, swi[(c + 1) * 3 + 0], i0b));
            i1b = fmaf(hB0, swi[c * 3 + 1], fmaf(hB1, swi[(c + 1) * 3 + 1], i1b));
            i2b = fmaf(hB0, swi[c * 3 + 2], fmaf(hB1, swi[(c + 1) * 3 + 2], i2b));
        } else {
            int c = col - 64;
            t0a = fmaf(hA0, swt[c * 2 + 0], fmaf(hA1, swt[(c + 1) * 2 + 0], t0a));
            t1a = fmaf(hA0, swt[c * 2 + 1], fmaf(hA1, swt[(c + 1) * 2 + 1], t1a));
            t0b = fmaf(hB0, swt[c * 2 + 0], fmaf(hB1, swt[(c + 1) * 2 + 0], t0b));
            t1b = fmaf(hB0, swt[c * 2 + 1], fmaf(hB1, swt[(c + 1) * 2 + 1], t1b));
        }
    }
#pragma unroll
    for (int off = 1; off <= 2; off <<= 1) {
        i0a += __shfl_xor_sync(0xffffffffu, i0a, off);
        i1a += __shfl_xor_sync(0xffffffffu, i1a, off);
        i2a += __shfl_xor_sync(0xffffffffu, i2a, off);
        t0a += __shfl_xor_sync(0xffffffffu, t0a, off);
        t1a += __shfl_xor_sync(0xffffffffu, t1a, off);
        i0b += __shfl_xor_sync(0xffffffffu, i0b, off);
        i1b += __shfl_xor_sync(0xffffffffu, i1b, off);
        i2b += __shfl_xor_sync(0xffffffffu, i2b, off);
        t0b += __shfl_xor_sync(0xffffffffu, t0b, off);
        t1b += __shfl_xor_sync(0xffffffffu, t1b, off);
    }
    if (t == 0) {
        int grow0 = rb + lrow0, grow1 = grow0 + 8;
        float bi0 = __ldg(b2i + 0), bi1 = __ldg(b2i + 1), bi2 = __ldg(b2i + 2);
        float bt0 = __ldg(b2t + 0), bt1 = __ldg(b2t + 1);
        if (grow0 < nrows) {
            out[grow0 * 3 + 0] = i0a + bi0;
            out[grow0 * 3 + 1] = i1a + bi1;
            out[grow0 * 3 + 2] = i2a + bi2;
            out[3 * NN + grow0 * 2 + 0] = softplusf(t0a + bt0);
            out[3 * NN + grow0 * 2 + 1] = softplusf(t1a + bt1);
        }
        if (grow1 < nrows) {
            out[grow1 * 3 + 0] = i0b + bi0;
            out[grow1 * 3 + 1] = i1b + bi1;
            out[grow1 * 3 + 2] = i2b + bi2;
            out[3 * NN + grow1 * 2 + 0] = softplusf(t0b + bt0);
            out[3 * NN + grow1 * 2 + 1] = softplusf(t1b + bt1);
        }
    }
}

// ---------------- edge weights: w = exp(leaky(es+ed)); no shift (|e| <~ 1, overflow-safe) ----------------
__global__ void __launch_bounds__(256) wgt_k() {
    int idx = blockIdx.x * blockDim.x + threadIdx.x;
    if (idx >= ET) return;
    int s = g_csrc[idx], d = g_cdst[idx];
    float4 esv = *(const float4*)(g_es + s * 4);
    float4 edv = *(const float4*)(g_ed + d * 4);
    float4 wv;
    {
        float e = esv.x + edv.x; e = (e > 0.f) ? e : 0.2f * e;
        wv.x = __expf(e);
    }
    {
        float e = esv.y + edv.y; e = (e > 0.f) ? e : 0.2f * e;
        wv.y = __expf(e);
    }
    {
        float e = esv.z + edv.z; e = (e > 0.f) ? e : 0.2f * e;
        wv.z = __expf(e);
    }
    {
        float e = esv.w + edv.w; e = (e > 0.f) ? e : 0.2f * e;
        wv.w = __expf(e);
    }
    *(float4*)(g_w + idx * 4) = wv;
}

// ---------------- gather: weighted aggregate + bias + residual + LN + relu + fp16 mirror ----------------
__global__ void __launch_bounds__(256) gather_k(float* __restrict__ h,
                                                const float* __restrict__ bc,
                                                const float* __restrict__ gam,
                                                const float* __restrict__ bet) {
    int d = (blockIdx.x * 256 + threadIdx.x) >> 5;
    if (d >= NN) return;
    int lane = threadIdx.x & 31;
    int hh = lane >> 3;
    int beg = g_rowstart[d], end = g_rowstart[d + 1];

    float ssum = 0.f;
    float4 acc = make_float4(0.f, 0.f, 0.f, 0.f);
    int i = beg;
    for (; i + 8 <= end; i += 8) {
        int s[8];
        float w[8];
        uint2 r[8];
#pragma unroll
        for (int j = 0; j < 8; j++) s[j] = __ldg(&g_csrc[i + j]);
#pragma unroll
        for (int j = 0; j < 8; j++) w[j] = __ldg(&g_w[(i + j) * 4 + hh]);
#pragma unroll
        for (int j = 0; j < 8; j++) r[j] = *(const uint2*)(g_xph + s[j] * 128 + lane * 4);
#pragma unroll
        for (int j = 0; j < 8; j++) {
            float2 a = __half22float2(*(__half2*)&r[j].x);
            float2 b = __half22float2(*(__half2*)&r[j].y);
            ssum += w[j];
            acc.x = fmaf(w[j], a.x, acc.x);
            acc.y = fmaf(w[j], a.y, acc.y);
            acc.z = fmaf(w[j], b.x, acc.z);
            acc.w = fmaf(w[j], b.y, acc.w);
        }
    }
    for (; i < end; i++) {
        int s0 = __ldg(&g_csrc[i]);
        float w0 = __ldg(&g_w[i * 4 + hh]);
        uint2 r0 = *(const uint2*)(g_xph + s0 * 128 + lane * 4);
        float2 a0 = __half22float2(*(__half2*)&r0.x), b0 = __half22float2(*(__half2*)&r0.y);
        ssum += w0;
        acc.x = fmaf(w0, a0.x, acc.x);
        acc.y = fmaf(w0, a0.y, acc.y);
        acc.z = fmaf(w0, b0.x, acc.z);
        acc.w = fmaf(w0, b0.y, acc.w);
    }
    float inv = 1.f / ssum;

    float4 hv = *(const float4*)(h + d * 128 + lane * 4);
    float4 bcv = *(const float4*)(bc + lane * 4);
    float4 y;
    y.x = acc.x * inv + bcv.x + hv.x;
    y.y = acc.y * inv + bcv.y + hv.y;
    y.z = acc.z * inv + bcv.z + hv.z;
    y.w = acc.w * inv + bcv.w + hv.w;

    float s1v = y.x + y.y + y.z + y.w;
#pragma unroll
    for (int off = 16; off >= 1; off >>= 1) s1v += __shfl_xor_sync(0xffffffffu, s1v, off);
    float mean = s1v * (1.f / 128.f);
    float dx = y.x - mean, dy = y.y - mean, dz = y.z - mean, dw = y.w - mean;
    float sq = dx * dx + dy * dy + dz * dz + dw * dw;
#pragma unroll
    for (int off = 16; off >= 1; off >>= 1) sq += __shfl_xor_sync(0xffffffffu, sq, off);
    float rstd = rsqrtf(sq * (1.f / 128.f) + 1e-5f);

    float4 g4 = *(const float4*)(gam + lane * 4);
    float4 b4 = *(const float4*)(bet + lane * 4);
    float4 o;
    o.x = fmaxf(dx * rstd * g4.x + b4.x, 0.f);
    o.y = fmaxf(dy * rstd * g4.y + b4.y, 0.f);
    o.z = fmaxf(dz * rstd * g4.z + b4.z, 0.f);
    o.w = fmaxf(dw * rstd * g4.w + b4.w, 0.f);
    *(float4*)(h + d * 128 + lane * 4) = o;
    // fp16 mirror for the next GEMM's A-feed
    __half2 m0 = __floats2half2_rn(o.x, o.y);
    __half2 m1 = __floats2half2_rn(o.z, o.w);
    *(uint2*)(g_hf16 + d * 128 + lane * 4) =
        make_uint2(*(uint32_t*)&m0, *(uint32_t*)&m1);
}

// ---------------- launch ----------------
extern "C" void kernel_launch(void* const* d_in, const int* in_sizes, int n_in,
                              void* d_out, int out_size) {
    const float* x      = (const float*)d_in[0];
    const int*   ei     = (const int*)d_in[1];
    const float* enc_w1 = (const float*)d_in[2];
    const float* enc_b1 = (const float*)d_in[3];
    const float* enc_w2 = (const float*)d_in[4];
    const float* enc_b2 = (const float*)d_in[5];
    const float* W[3]  = {(const float*)d_in[6],  (const float*)d_in[12], (const float*)d_in[18]};
    const float* As[3] = {(const float*)d_in[7],  (const float*)d_in[13], (const float*)d_in[19]};
    const float* Ad[3] = {(const float*)d_in[8],  (const float*)d_in[14], (const float*)d_in[20]};
    const float* Bc[3] = {(const float*)d_in[9],  (const float*)d_in[15], (const float*)d_in[21]};
    const float* Gm[3] = {(const float*)d_in[10], (const float*)d_in[16], (const float*)d_in[22]};
    const float* Be[3] = {(const float*)d_in[11], (const float*)d_in[17], (const float*)d_in[23]};
    const float* imp_w1 = (const float*)d_in[24];
    const float* imp_b1 = (const float*)d_in[25];
    const float* imp_w2 = (const float*)d_in[26];
    const float* imp_b2 = (const float*)d_in[27];
    const float* tim_w1 = (const float*)d_in[28];
    const float* tim_b1 = (const float*)d_in[29];
    const float* tim_w2 = (const float*)d_in[30];
    const float* tim_b2 = (const float*)d_in[31];
    float* out = (float*)d_out;

    float* p_h;
    cudaGetSymbolAddress((void**)&p_h, g_h);
    __half* p_hf16;
    cudaGetSymbolAddress((void**)&p_hf16, g_hf16);
    __half* p_w16;
    cudaGetSymbolAddress((void**)&p_w16, g_w16);

    const int SMEM_128 = 34816 + 128 * LDB;  // 69632
    cudaFuncSetAttribute((const void*)mma_gemm_k<128>,
                         cudaFuncAttributeMaxDynamicSharedMemorySize, SMEM_128);
    cudaFuncSetAttribute((const void*)mma_heads_k,
                         cudaFuncAttributeMaxDynamicSharedMemorySize, SMEM_128);
    cudaFuncSetAttribute((const void*)enc_fused_k,
                         cudaFuncAttributeMaxDynamicSharedMemorySize, SMEM_128);

    const int NB = (NN + 127) / 128;  // 391

    // weight prep (+deg zero) + CSR build
    prep_w_k<<<7 + SCAN_B, 256>>>(enc_w2, W[0], W[1], W[2], imp_w1, tim_w1, enc_w1);
    count_k<<<(EE / 4 + 255) / 256, 256>>>(ei);
    partial_k<<<SCAN_B, 256>>>();
    fill_k<<<SCAN_B, 256>>>();
    scatter_k<<<(EE / 4 + 255) / 256, 256>>>(ei);

    // fused encoder (writes h fp32 + fp16 mirror)
    enc_fused_k<<<NB, 256, SMEM_128>>>(x, enc_b1, p_w16, enc_b2, p_h, NN);

    // 3 GAT layers: GEMM(es/ed/fp16 xp) -> edge-parallel weights -> gather (+mirror)
    for (int l = 0; l < 3; l++) {
        mma_gemm_k<128><<<NB, 256, SMEM_128>>>(
            p_hf16, p_w16 + (1 + l) * 16384, As[l], Ad[l], NN);
        wgt_k<<<(ET + 255) / 256, 256>>>();
        gather_k<<<(NN * 32 + 255) / 256, 256>>>(p_h, Bc[l], Gm[l], Be[l]);
    }

    // fully fused heads (GEMM + relu + second layer + softplus)
    mma_heads_k<<<NB, 256, SMEM_128>>>(p_hf16, p_w16 + 4 * 16384, imp_b1, tim_b1,
                                       imp_w2, imp_b2, tim_w2, tim_b2, out, NN);
}

// round 17
// speedup vs baseline: 1.0938x; 1.0938x over previous
#include <cuda_runtime.h>
#include <cuda_fp16.h>
#include <math.h>
#include <stdint.h>

#define NN 50000
#define EE 1600000
#define ET (EE + NN)
#define HID 128
#define FIN 39

#define SCAN_B 256
#define SCAN_CH ((NN + SCAN_B - 1) / SCAN_B)  // 196 nodes per scan block

// ---------------- scratch (device globals; no allocation allowed) ----------------
__device__ float g_h[NN * HID];
__device__ __half g_hf16[NN * HID];  // fp16 mirror of h (A-feed for all GEMMs)
__device__ __half g_xph[NN * HID];   // fp16 xp (gather is the only consumer)
__device__ float g_es[NN * 4];
__device__ float g_ed[NN * 4];
__device__ int g_deg[NN];
__device__ int g_rowstart[NN + 1];
__device__ int g_cursor[NN];
__device__ int g_csrc[ET];
__device__ int g_bsum[SCAN_B];
// pre-converted fp16 weight images, linear [N][K]
__device__ __half g_w16[6 * 128 * 128];
__device__ __half g_w1h[128 * 48];  // enc_w1 hi, [N=128][K=48] (39 real + pad)
__device__ __half g_w1l[128 * 48];  // enc_w1 lo

// ---------------- CSR build (deg zeroed in prep_w_k; self-loop folded in as +1) ----------------
__global__ void count_k(const int* __restrict__ ei) {
    int idx = blockIdx.x * blockDim.x + threadIdx.x;  // 4 edges each
    int e0 = idx * 4;
    if (e0 >= EE) return;
    int4 d = *(const int4*)(ei + EE + e0);
    atomicAdd(&g_deg[d.x], 1);
    atomicAdd(&g_deg[d.y], 1);
    atomicAdd(&g_deg[d.z], 1);
    atomicAdd(&g_deg[d.w], 1);
}

// phase 1: per-block chunk sums of (deg+1)
__global__ void __launch_bounds__(256) partial_k() {
    __shared__ int ws[8];
    int b = blockIdx.x, t = threadIdx.x;
    int lo = b * SCAN_CH, hi = min(lo + SCAN_CH, NN);
    int s = 0;
    for (int i = lo + t; i < hi; i += 256) s += g_deg[i] + 1;
#pragma unroll
    for (int off = 16; off >= 1; off >>= 1) s += __shfl_xor_sync(0xffffffffu, s, off);
    if ((t & 31) == 0) ws[t >> 5] = s;
    __syncthreads();
    if (t < 8) {
        int v = ws[t];
#pragma unroll
        for (int off = 4; off >= 1; off >>= 1) v += __shfl_xor_sync(0xffu, v, off);
        if (t == 0) g_bsum[b] = v;
    }
}

// phase 2+3 merged: each block reduces bsum[0..b-1] itself, then local re-scan + write
__global__ void __launch_bounds__(256) fill_k() {
    __shared__ int sh[256];
    __shared__ int part[8];
    int b = blockIdx.x, t = threadIdx.x;
    {
        int v = (t < b) ? g_bsum[t] : 0;
#pragma unroll
        for (int off = 16; off >= 1; off >>= 1) v += __shfl_xor_sync(0xffffffffu, v, off);
        if ((t & 31) == 0) part[t >> 5] = v;
    }
    if (b == 0 && t == 0) g_rowstart[NN] = ET;
    int lo = b * SCAN_CH, hi = min(lo + SCAN_CH, NN);
    const int CH2 = (SCAN_CH + 255) / 256;  // 1
    int mylo = lo + t * CH2;
    int myhi = min(mylo + CH2, hi);
    int s = 0;
    for (int i = mylo; i < myhi; i++) s += g_deg[i] + 1;
    sh[t] = s;
    __syncthreads();
    for (int off = 1; off < 256; off <<= 1) {
        int u = (t >= off) ? sh[t - off] : 0;
        __syncthreads();
        sh[t] += u;
        __syncthreads();
    }
    int pbase = 0;
#pragma unroll
    for (int j = 0; j < 8; j++) pbase += part[j];
    int base = pbase + ((t == 0) ? 0 : sh[t - 1]);
    for (int i = mylo; i < myhi; i++) {
        g_rowstart[i] = base;
        g_csrc[base] = i;  // self-loop
        g_cursor[i] = base + 1;
        base += g_deg[i] + 1;
    }
}

__global__ void scatter_k(const int* __restrict__ ei) {
    int idx = blockIdx.x * blockDim.x + threadIdx.x;  // 4 edges each
    int e0 = idx * 4;
    if (e0 >= EE) return;
    int4 sv = *(const int4*)(ei + e0);
    int4 dv = *(const int4*)(ei + EE + e0);
    int p0 = atomicAdd(&g_cursor[dv.x], 1);
    g_csrc[p0] = sv.x;
    int p1 = atomicAdd(&g_cursor[dv.y], 1);
    g_csrc[p1] = sv.y;
    int p2 = atomicAdd(&g_cursor[dv.z], 1);
    g_csrc[p2] = sv.z;
    int p3 = atomicAdd(&g_cursor[dv.w], 1);
    g_csrc[p3] = sv.w;
}

// ---------------- weight prep (+ deg zero) ----------------
__global__ void __launch_bounds__(256) prep_w_k(const float* __restrict__ w0,
                                                const float* __restrict__ w1,
                                                const float* __restrict__ w2,
                                                const float* __restrict__ w3,
                                                const float* __restrict__ w4,
                                                const float* __restrict__ w5,
                                                const float* __restrict__ we1) {
    int m = blockIdx.x;
    if (m >= 7) {  // blocks 7.. zero g_deg
        int b = m - 7;
        int lo = b * SCAN_CH, hi = min(lo + SCAN_CH, NN);
        for (int i = lo + threadIdx.x; i < hi; i += 256) g_deg[i] = 0;
        return;
    }
    if (m == 6) {
        for (int i = threadIdx.x; i < 128 * 48; i += 256) {
            int n = i / 48, k = i % 48;
            float v = (k < FIN) ? we1[k * 128 + n] : 0.f;
            __half h = __float2half_rn(v);
            g_w1h[i] = h;
            g_w1l[i] = __float2half_rn(v - __half2float(h));
        }
        return;
    }
    const float* Wm[6] = {w0, w1, w2, w3, w4, w5};
    const int ncs[6] = {128, 128, 128, 128, 64, 64};
    const int bases[6] = {0, 16384, 32768, 49152, 65536, 65536 + 8192};  // imp+tim packed
    const float* B = Wm[m];
    int NC = ncs[m];
    __half* dst = g_w16 + bases[m];
    int total = NC * 128;
    for (int i = threadIdx.x; i < total; i += 256) {
        int n = i >> 7, k = i & 127;
        dst[i] = __float2half_rn(B[k * NC + n]);
    }
}

// ---------------- HMMA GEMM core pieces (single-pass fp16) ----------------
#define LDB 272   // padded smem row stride, K=128 tiles
#define LDA1 112  // padded smem row stride, K=48 tiles

#define MMA16816(d, A0, A1, A2, A3, B0, B1)                                     \
    asm volatile(                                                               \
        "mma.sync.aligned.m16n8k16.row.col.f32.f16.f16.f32 "                    \
        "{%0,%1,%2,%3}, {%4,%5,%6,%7}, {%8,%9}, {%0,%1,%2,%3};"                 \
        : "+f"((d)[0]), "+f"((d)[1]), "+f"((d)[2]), "+f"((d)[3])                \
        : "r"(A0), "r"(A1), "r"(A2), "r"(A3), "r"(B0), "r"(B1))

// fill A (pre-converted fp16 mirror) + B (pre-converted) into padded smem — pure copies
template <int NC>
__device__ __forceinline__ void gemm_fill16(const __half* A16, const __half* B16,
                                            char* sA, char* sB,
                                            int rb, int nrows, int tid) {
    for (int i = tid; i < 128 * 16; i += 256) {
        int r = i >> 4, u = i & 15;
        uint4 v = make_uint4(0, 0, 0, 0);
        if (rb + r < nrows) v = *(const uint4*)(A16 + (rb + r) * 128 + u * 8);
        *(uint4*)(sA + r * LDB + u * 16) = v;
    }
    for (int i = tid; i < NC * 16; i += 256) {
        int n = i >> 4, k8 = (i & 15) * 8;
        *(uint4*)(sB + n * LDB + k8 * 2) = ((const uint4*)B16)[i];
    }
}

template <int NCH>
__device__ __forceinline__ void gemm_main(const char* sA, const char* sB,
                                          int lrow0, int g, int t, float acc[][4]) {
#pragma unroll
    for (int n = 0; n < NCH; n++)
#pragma unroll
        for (int j = 0; j < 4; j++) acc[n][j] = 0.f;
#pragma unroll
    for (int ks = 0; ks < 8; ks++) {
        int kb = ks * 32 + t * 4;
        const char* pa = sA + lrow0 * LDB + kb;
        uint32_t a0 = *(const uint32_t*)(pa);
        uint32_t a1 = *(const uint32_t*)(pa + 8 * LDB);
        uint32_t a2 = *(const uint32_t*)(pa + 16);
        uint32_t a3 = *(const uint32_t*)(pa + 8 * LDB + 16);
#pragma unroll
        for (int n = 0; n < NCH; n++) {
            int col = n * 8 + g;
            const char* pb = sB + col * LDB + kb;
            uint32_t b0 = *(const uint32_t*)(pb);
            uint32_t b1 = *(const uint32_t*)(pb + 16);
            MMA16816(acc[n], a0, a1, a2, a3, b0, b1);
        }
    }
}

// ---------------- fused encoder: relu(x@W1+b1)@W2 + b2 in one block pass ----------------
__global__ void __launch_bounds__(256, 2) enc_fused_k(const float* __restrict__ x,
                                                      const float* __restrict__ b1,
                                                      const __half* __restrict__ w2,
                                                      const float* __restrict__ b2,
                                                      float* __restrict__ H, int nrows) {
    extern __shared__ char smem[];
    char* sA1h = smem;             // 128*112 = 14336
    char* sA1l = smem + 14336;
    char* sB1h = smem + 28672;
    char* sB1l = smem + 43008;
    __shared__ float sb1[128];

    int tid = threadIdx.x;
    int rb = blockIdx.x * 128;
    if (tid < 128) sb1[tid] = b1[tid];

    for (int i = tid; i < 14336 / 16; i += 256) {
        ((uint4*)sA1h)[i] = make_uint4(0, 0, 0, 0);
        ((uint4*)sA1l)[i] = make_uint4(0, 0, 0, 0);
    }
    for (int i = tid; i < 128 * 6; i += 256) {
        int n = i / 6, u = i % 6;
        *(uint4*)(sB1h + n * LDA1 + u * 16) = ((const uint4*)g_w1h)[i];
        *(uint4*)(sB1l + n * LDA1 + u * 16) = ((const uint4*)g_w1l)[i];
    }
    __syncthreads();
    for (int i = tid; i < 128 * FIN; i += 256) {
        int r = i / FIN, c = i % FIN;
        float v = (rb + r < nrows) ? x[(rb + r) * FIN + c] : 0.f;
        __half h = __float2half_rn(v);
        *(__half*)(sA1h + r * LDA1 + c * 2) = h;
        *(__half*)(sA1l + r * LDA1 + c * 2) = __float2half_rn(v - __half2float(h));
    }
    __syncthreads();

    int wid = tid >> 5, lane = tid & 31;
    int g = lane >> 2, t = lane & 3;
    int lrow0 = wid * 16 + g;

    float acc[16][4];
#pragma unroll
    for (int n = 0; n < 16; n++)
#pragma unroll
        for (int j = 0; j < 4; j++) acc[n][j] = 0.f;

#pragma unroll
    for (int ks = 0; ks < 3; ks++) {
        int kb = ks * 32 + t * 4;
        const char* ph = sA1h + lrow0 * LDA1 + kb;
        uint32_t ah0 = *(const uint32_t*)(ph);
        uint32_t ah1 = *(const uint32_t*)(ph + 8 * LDA1);
        uint32_t ah2 = *(const uint32_t*)(ph + 16);
        uint32_t ah3 = *(const uint32_t*)(ph + 8 * LDA1 + 16);
        const char* pl = sA1l + lrow0 * LDA1 + kb;
        uint32_t al0 = *(const uint32_t*)(pl);
        uint32_t al1 = *(const uint32_t*)(pl + 8 * LDA1);
        uint32_t al2 = *(const uint32_t*)(pl + 16);
        uint32_t al3 = *(const uint32_t*)(pl + 8 * LDA1 + 16);
#pragma unroll
        for (int n = 0; n < 16; n++) {
            int col = n * 8 + g;
            const char* pbh = sB1h + col * LDA1 + kb;
            uint32_t bh0 = *(const uint32_t*)(pbh);
            uint32_t bh1 = *(const uint32_t*)(pbh + 16);
            const char* pbl = sB1l + col * LDA1 + kb;
            uint32_t bl0 = *(const uint32_t*)(pbl);
            uint32_t bl1 = *(const uint32_t*)(pbl + 16);
            MMA16816(acc[n], ah0, ah1, ah2, ah3, bh0, bh1);
            MMA16816(acc[n], ah0, ah1, ah2, ah3, bl0, bl1);
            MMA16816(acc[n], al0, al1, al2, al3, bh0, bh1);
        }
    }
    __syncthreads();

    char* sA2 = smem;
    char* sB2 = smem + 34816;
#pragma unroll
    for (int n = 0; n < 16; n++) {
        int col = n * 8 + t * 2;
        float v0 = fmaxf(acc[n][0] + sb1[col], 0.f);
        float v1 = fmaxf(acc[n][1] + sb1[col + 1], 0.f);
        float v2 = fmaxf(acc[n][2] + sb1[col], 0.f);
        float v3 = fmaxf(acc[n][3] + sb1[col + 1], 0.f);
        __half2 p0 = __floats2half2_rn(v0, v1);
        __half2 p1 = __floats2half2_rn(v2, v3);
        *(__half2*)(sA2 + lrow0 * LDB + col * 2) = p0;
        *(__half2*)(sA2 + (lrow0 + 8) * LDB + col * 2) = p1;
    }
    for (int i = tid; i < 128 * 16; i += 256) {
        int n = i >> 4, k8 = (i & 15) * 8;
        *(uint4*)(sB2 + n * LDB + k8 * 2) = ((const uint4*)w2)[i];
    }
    __syncthreads();

    float acc2[16][4];
    gemm_main<16>(sA2, sB2, lrow0, g, t, acc2);

    int grow0 = rb + lrow0, grow1 = grow0 + 8;
#pragma unroll
    for (int n = 0; n < 16; n++) {
        int col = n * 8 + t * 2;
        float b0 = __ldg(b2 + col), b1v = __ldg(b2 + col + 1);
        float o0 = acc2[n][0] + b0, o1 = acc2[n][1] + b1v;
        float o2 = acc2[n][2] + b0, o3 = acc2[n][3] + b1v;
        if (grow0 < nrows) {
            *(float2*)(H + grow0 * 128 + col) = make_float2(o0, o1);
            __half2 m0 = __floats2half2_rn(o0, o1);
            *(__half2*)(g_hf16 + grow0 * 128 + col) = m0;
        }
        if (grow1 < nrows) {
            *(float2*)(H + grow1 * 128 + col) = make_float2(o2, o3);
            __half2 m1 = __floats2half2_rn(o2, o3);
            *(__half2*)(g_hf16 + grow1 * 128 + col) = m1;
        }
    }
}

// main GEMM (ATTN): A from fp16 mirror; writes fp16 xp + es/ed
template <int NC>
__global__ void __launch_bounds__(256, 2) mma_gemm_k(const __half* __restrict__ A16,
                                                     const __half* __restrict__ B16,
                                                     const float* __restrict__ a_s,
                                                     const float* __restrict__ a_d,
                                                     int nrows) {
    extern __shared__ char smem[];
    char* sA = smem;            // 128*272 = 34816
    char* sB = smem + 34816;    // NC*272

    int tid = threadIdx.x;
    int rb = blockIdx.x * 128;
    gemm_fill16<NC>(A16, B16, sA, sB, rb, nrows, tid);
    __syncthreads();

    int wid = tid >> 5, lane = tid & 31;
    int g = lane >> 2, t = lane & 3;
    int lrow0 = wid * 16 + g;
    constexpr int NCH = NC / 8;
    float acc[NCH][4];
    gemm_main<NCH>(sA, sB, lrow0, g, t, acc);

    int grow0 = rb + lrow0, grow1 = grow0 + 8;

    float es0[4], ed0[4], es1[4], ed1[4];
#pragma unroll
    for (int h = 0; h < 4; h++) { es0[h] = 0.f; ed0[h] = 0.f; es1[h] = 0.f; ed1[h] = 0.f; }
#pragma unroll
    for (int n = 0; n < NCH; n++) {
        int col = n * 8 + t * 2;
        int h = n >> 2;
        float as0 = __ldg(a_s + col), as1 = __ldg(a_s + col + 1);
        float ad0 = __ldg(a_d + col), ad1 = __ldg(a_d + col + 1);
        es0[h] += acc[n][0] * as0 + acc[n][1] * as1;
        ed0[h] += acc[n][0] * ad0 + acc[n][1] * ad1;
        es1[h] += acc[n][2] * as0 + acc[n][3] * as1;
        ed1[h] += acc[n][2] * ad0 + acc[n][3] * ad1;
    }
#pragma unroll
    for (int h = 0; h < 4; h++) {
        es0[h] += __shfl_xor_sync(0xffffffffu, es0[h], 1);
        es0[h] += __shfl_xor_sync(0xffffffffu, es0[h], 2);
        ed0[h] += __shfl_xor_sync(0xffffffffu, ed0[h], 1);
        ed0[h] += __shfl_xor_sync(0xffffffffu, ed0[h], 2);
        es1[h] += __shfl_xor_sync(0xffffffffu, es1[h], 1);
        es1[h] += __shfl_xor_sync(0xffffffffu, es1[h], 2);
        ed1[h] += __shfl_xor_sync(0xffffffffu, ed1[h], 1);
        ed1[h] += __shfl_xor_sync(0xffffffffu, ed1[h], 2);
    }
    if (t == 0) {
        if (grow0 < nrows) {
#pragma unroll
            for (int h = 0; h < 4; h++) {
                g_es[grow0 * 4 + h] = es0[h];
                g_ed[grow0 * 4 + h] = ed0[h];
            }
        }
        if (grow1 < nrows) {
#pragma unroll
            for (int h = 0; h < 4; h++) {
                g_es[grow1 * 4 + h] = es1[h];
                g_ed[grow1 * 4 + h] = ed1[h];
            }
        }
    }
#pragma unroll
    for (int n = 0; n < NCH; n++) {
        int col = n * 8 + t * 2;
        __half2 p0 = __floats2half2_rn(acc[n][0], acc[n][1]);
        __half2 p1 = __floats2half2_rn(acc[n][2], acc[n][3]);
        if (grow0 < nrows) *(__half2*)(g_xph + grow0 * NC + col) = p0;
        if (grow1 < nrows) *(__half2*)(g_xph + grow1 * NC + col) = p1;
    }
}

// ---------------- softplus ----------------
__device__ __forceinline__ float softplusf(float x) {
    if (x > 20.f) return x;
    return log1pf(__expf(x));
}

// fused heads: GEMM([imp_w1|tim_w1]) + relu + second-layer dots + softplus
__global__ void __launch_bounds__(256, 2) mma_heads_k(const __half* __restrict__ A16,
                                                      const __half* __restrict__ B16,
                                                      const float* __restrict__ biasA,
                                                      const float* __restrict__ biasB,
                                                      const float* __restrict__ w2i,
                                                      const float* __restrict__ b2i,
                                                      const float* __restrict__ w2t,
                                                      const float* __restrict__ b2t,
                                                      float* __restrict__ out,
                                                      int nrows) {
    extern __shared__ char smem[];
    char* sA = smem;
    char* sB = smem + 34816;
    __shared__ float swi[192];
    __shared__ float swt[128];
    __shared__ float sbias[128];

    int tid = threadIdx.x;
    if (tid < 192) swi[tid] = w2i[tid];
    if (tid < 128) swt[tid] = w2t[tid];
    if (tid < 64) sbias[tid] = biasA[tid];
    else if (tid < 128) sbias[tid] = biasB[tid - 64];

    int rb = blockIdx.x * 128;
    gemm_fill16<128>(A16, B16, sA, sB, rb, nrows, tid);
    __syncthreads();

    int wid = tid >> 5, lane = tid & 31;
    int g = lane >> 2, t = lane & 3;
    int lrow0 = wid * 16 + g;
    float acc[16][4];
    gemm_main<16>(sA, sB, lrow0, g, t, acc);

    float i0a = 0.f, i1a = 0.f, i2a = 0.f, t0a = 0.f, t1a = 0.f;
    float i0b = 0.f, i1b = 0.f, i2b = 0.f, t0b = 0.f, t1b = 0.f;
#pragma unroll
    for (int n = 0; n < 16; n++) {
        int col = n * 8 + t * 2;
        float bb0 = sbias[col], bb1 = sbias[col + 1];
        float hA0 = fmaxf(acc[n][0] + bb0, 0.f), hA1 = fmaxf(acc[n][1] + bb1, 0.f);
        float hB0 = fmaxf(acc[n][2] + bb0, 0.f), hB1 = fmaxf(acc[n][3] + bb1, 0.f);
        if (col < 64) {
            int c = col;
            i0a = fmaf(hA0, swi[c * 3 + 0], fmaf(hA1, swi[(c + 1) * 3 + 0], i0a));
            i1a = fmaf(hA0, swi[c * 3 + 1], fmaf(hA1, swi[(c + 1) * 3 + 1], i1a));
            i2a = fmaf(hA0, swi[c * 3 + 2], fmaf(hA1, swi[(c + 1) * 3 + 2], i2a));
            i0b = fmaf(hB0, swi[c * 3 + 0], fmaf(hB1, swi[(c + 1) * 3 + 0], i0b));
            i1b = fmaf(hB0, swi[c * 3 + 1], fmaf(hB1, swi[(c + 1) * 3 + 1], i1b));
            i2b = fmaf(hB0, swi[c * 3 + 2], fmaf(hB1, swi[(c + 1) * 3 + 2], i2b));
        } else {
            int c = col - 64;
            t0a = fmaf(hA0, swt[c * 2 + 0], fmaf(hA1, swt[(c + 1) * 2 + 0], t0a));
            t1a = fmaf(hA0, swt[c * 2 + 1], fmaf(hA1, swt[(c + 1) * 2 + 1], t1a));
            t0b = fmaf(hB0, swt[c * 2 + 0], fmaf(hB1, swt[(c + 1) * 2 + 0], t0b));
            t1b = fmaf(hB0, swt[c * 2 + 1], fmaf(hB1, swt[(c + 1) * 2 + 1], t1b));
        }
    }
#pragma unroll
    for (int off = 1; off <= 2; off <<= 1) {
        i0a += __shfl_xor_sync(0xffffffffu, i0a, off);
        i1a += __shfl_xor_sync(0xffffffffu, i1a, off);
        i2a += __shfl_xor_sync(0xffffffffu, i2a, off);
        t0a += __shfl_xor_sync(0xffffffffu, t0a, off);
        t1a += __shfl_xor_sync(0xffffffffu, t1a, off);
        i0b += __shfl_xor_sync(0xffffffffu, i0b, off);
        i1b += __shfl_xor_sync(0xffffffffu, i1b, off);
        i2b += __shfl_xor_sync(0xffffffffu, i2b, off);
        t0b += __shfl_xor_sync(0xffffffffu, t0b, off);
        t1b += __shfl_xor_sync(0xffffffffu, t1b, off);
    }
    if (t == 0) {
        int grow0 = rb + lrow0, grow1 = grow0 + 8;
        float bi0 = __ldg(b2i + 0), bi1 = __ldg(b2i + 1), bi2 = __ldg(b2i + 2);
        float bt0 = __ldg(b2t + 0), bt1 = __ldg(b2t + 1);
        if (grow0 < nrows) {
            out[grow0 * 3 + 0] = i0a + bi0;
            out[grow0 * 3 + 1] = i1a + bi1;
            out[grow0 * 3 + 2] = i2a + bi2;
            out[3 * NN + grow0 * 2 + 0] = softplusf(t0a + bt0);
            out[3 * NN + grow0 * 2 + 1] = softplusf(t1a + bt1);
        }
        if (grow1 < nrows) {
            out[grow1 * 3 + 0] = i0b + bi0;
            out[grow1 * 3 + 1] = i1b + bi1;
            out[grow1 * 3 + 2] = i2b + bi2;
            out[3 * NN + grow1 * 2 + 0] = softplusf(t0b + bt0);
            out[3 * NN + grow1 * 2 + 1] = softplusf(t1b + bt1);
        }
    }
}

// ---------------- gather: fused weight computation (lane-transpose) + aggregate + LN ----------------
// 8-edge block: lane l computes w for (edge = l&7, head = l>>3) — 32 values, one per lane,
// one expf instruction — then shfl redistributes. Zero redundancy.
__global__ void __launch_bounds__(256) gather_k(float* __restrict__ h,
                                                const float* __restrict__ bc,
                                                const float* __restrict__ gam,
                                                const float* __restrict__ bet) {
    int d = (blockIdx.x * 256 + threadIdx.x) >> 5;
    if (d >= NN) return;
    int lane = threadIdx.x & 31;
    int hh = lane >> 3;
    float edc = g_ed[d * 4 + hh];
    int beg = g_rowstart[d], end = g_rowstart[d + 1];

    float ssum = 0.f;
    float4 acc = make_float4(0.f, 0.f, 0.f, 0.f);
    int i = beg;
    int base_l = lane & 24;
    for (; i + 8 <= end; i += 8) {
        // compute role: edge j8 = lane&7, head hh = lane>>3
        int sj = __ldg(&g_csrc[i + (lane & 7)]);
        float esv = __ldg(&g_es[sj * 4 + hh]);
        float e = esv + edc;
        e = (e > 0.f) ? e : 0.2f * e;
        float wf = __expf(e);
        float w[8];
        int s[8];
#pragma unroll
        for (int j = 0; j < 8; j++) {
            w[j] = __shfl_sync(0xffffffffu, wf, base_l + j);
            s[j] = __shfl_sync(0xffffffffu, sj, j);
        }
        uint2 r[8];
#pragma unroll
        for (int j = 0; j < 8; j++) r[j] = *(const uint2*)(g_xph + s[j] * 128 + lane * 4);
#pragma unroll
        for (int j = 0; j < 8; j++) {
            float2 a = __half22float2(*(__half2*)&r[j].x);
            float2 b = __half22float2(*(__half2*)&r[j].y);
            ssum += w[j];
            acc.x = fmaf(w[j], a.x, acc.x);
            acc.y = fmaf(w[j], a.y, acc.y);
            acc.z = fmaf(w[j], b.x, acc.z);
            acc.w = fmaf(w[j], b.y, acc.w);
        }
    }
    for (; i < end; i++) {
        int s0 = __ldg(&g_csrc[i]);
        float esv = __ldg(&g_es[s0 * 4 + hh]);
        float e = esv + edc;
        e = (e > 0.f) ? e : 0.2f * e;
        float w0 = __expf(e);
        uint2 r0 = *(const uint2*)(g_xph + s0 * 128 + lane * 4);
        float2 a0 = __half22float2(*(__half2*)&r0.x), b0 = __half22float2(*(__half2*)&r0.y);
        ssum += w0;
        acc.x = fmaf(w0, a0.x, acc.x);
        acc.y = fmaf(w0, a0.y, acc.y);
        acc.z = fmaf(w0, b0.x, acc.z);
        acc.w = fmaf(w0, b0.y, acc.w);
    }
    float inv = 1.f / ssum;

    float4 hv = *(const float4*)(h + d * 128 + lane * 4);
    float4 bcv = *(const float4*)(bc + lane * 4);
    float4 y;
    y.x = acc.x * inv + bcv.x + hv.x;
    y.y = acc.y * inv + bcv.y + hv.y;
    y.z = acc.z * inv + bcv.z + hv.z;
    y.w = acc.w * inv + bcv.w + hv.w;

    float s1v = y.x + y.y + y.z + y.w;
#pragma unroll
    for (int off = 16; off >= 1; off >>= 1) s1v += __shfl_xor_sync(0xffffffffu, s1v, off);
    float mean = s1v * (1.f / 128.f);
    float dx = y.x - mean, dy = y.y - mean, dz = y.z - mean, dw = y.w - mean;
    float sq = dx * dx + dy * dy + dz * dz + dw * dw;
#pragma unroll
    for (int off = 16; off >= 1; off >>= 1) sq += __shfl_xor_sync(0xffffffffu, sq, off);
    float rstd = rsqrtf(sq * (1.f / 128.f) + 1e-5f);

    float4 g4 = *(const float4*)(gam + lane * 4);
    float4 b4 = *(const float4*)(bet + lane * 4);
    float4 o;
    o.x = fmaxf(dx * rstd * g4.x + b4.x, 0.f);
    o.y = fmaxf(dy * rstd * g4.y + b4.y, 0.f);
    o.z = fmaxf(dz * rstd * g4.z + b4.z, 0.f);
    o.w = fmaxf(dw * rstd * g4.w + b4.w, 0.f);
    *(float4*)(h + d * 128 + lane * 4) = o;
    // fp16 mirror for the next GEMM's A-feed
    __half2 m0 = __floats2half2_rn(o.x, o.y);
    __half2 m1 = __floats2half2_rn(o.z, o.w);
    *(uint2*)(g_hf16 + d * 128 + lane * 4) =
        make_uint2(*(uint32_t*)&m0, *(uint32_t*)&m1);
}

// ---------------- launch ----------------
extern "C" void kernel_launch(void* const* d_in, const int* in_sizes, int n_in,
                              void* d_out, int out_size) {
    const float* x      = (const float*)d_in[0];
    const int*   ei     = (const int*)d_in[1];
    const float* enc_w1 = (const float*)d_in[2];
    const float* enc_b1 = (const float*)d_in[3];
    const float* enc_w2 = (const float*)d_in[4];
    const float* enc_b2 = (const float*)d_in[5];
    const float* W[3]  = {(const float*)d_in[6],  (const float*)d_in[12], (const float*)d_in[18]};
    const float* As[3] = {(const float*)d_in[7],  (const float*)d_in[13], (const float*)d_in[19]};
    const float* Ad[3] = {(const float*)d_in[8],  (const float*)d_in[14], (const float*)d_in[20]};
    const float* Bc[3] = {(const float*)d_in[9],  (const float*)d_in[15], (const float*)d_in[21]};
    const float* Gm[3] = {(const float*)d_in[10], (const float*)d_in[16], (const float*)d_in[22]};
    const float* Be[3] = {(const float*)d_in[11], (const float*)d_in[17], (const float*)d_in[23]};
    const float* imp_w1 = (const float*)d_in[24];
    const float* imp_b1 = (const float*)d_in[25];
    const float* imp_w2 = (const float*)d_in[26];
    const float* imp_b2 = (const float*)d_in[27];
    const float* tim_w1 = (const float*)d_in[28];
    const float* tim_b1 = (const float*)d_in[29];
    const float* tim_w2 = (const float*)d_in[30];
    const float* tim_b2 = (const float*)d_in[31];
    float* out = (float*)d_out;

    float* p_h;
    cudaGetSymbolAddress((void**)&p_h, g_h);
    __half* p_hf16;
    cudaGetSymbolAddress((void**)&p_hf16, g_hf16);
    __half* p_w16;
    cudaGetSymbolAddress((void**)&p_w16, g_w16);

    const int SMEM_128 = 34816 + 128 * LDB;  // 69632
    cudaFuncSetAttribute((const void*)mma_gemm_k<128>,
                         cudaFuncAttributeMaxDynamicSharedMemorySize, SMEM_128);
    cudaFuncSetAttribute((const void*)mma_heads_k,
                         cudaFuncAttributeMaxDynamicSharedMemorySize, SMEM_128);
    cudaFuncSetAttribute((const void*)enc_fused_k,
                         cudaFuncAttributeMaxDynamicSharedMemorySize, SMEM_128);

    const int NB = (NN + 127) / 128;  // 391

    // weight prep (+deg zero) + CSR build
    prep_w_k<<<7 + SCAN_B, 256>>>(enc_w2, W[0], W[1], W[2], imp_w1, tim_w1, enc_w1);
    count_k<<<(EE / 4 + 255) / 256, 256>>>(ei);
    partial_k<<<SCAN_B, 256>>>();
    fill_k<<<SCAN_B, 256>>>();
    scatter_k<<<(EE / 4 + 255) / 256, 256>>>(ei);

    // fused encoder (writes h fp32 + fp16 mirror)
    enc_fused_k<<<NB, 256, SMEM_128>>>(x, enc_b1, p_w16, enc_b2, p_h, NN);

    // 3 GAT layers: GEMM(es/ed/fp16 xp) -> gather (fused weights + mirror)
    for (int l = 0; l < 3; l++) {
        mma_gemm_k<128><<<NB, 256, SMEM_128>>>(
            p_hf16, p_w16 + (1 + l) * 16384, As[l], Ad[l], NN);
        gather_k<<<(NN * 32 + 255) / 256, 256>>>(p_h, Bc[l], Gm[l], Be[l]);
    }

    // fully fused heads (GEMM + relu + second layer + softplus)
    mma_heads_k<<<NB, 256, SMEM_128>>>(p_hf16, p_w16 + 4 * 16384, imp_b1, tim_b1,
                                       imp_w2, imp_b2, tim_w2, tim_b2, out, NN);
}